// round 1
// baseline (speedup 1.0000x reference)
#include <cuda_runtime.h>
#include <cstdint>

// Problem constants (fixed by reference _build_structures with seed 0)
#define GG       128
#define NPER     20
#define NNODES   (GG * NPER)          // 2560
#define P2       190                  // C(20,2)
#define N2       (GG * P2)            // 24320
#define P3       1140                 // C(20,3)
#define N3       (GG * P3)            // 145920
#define H        64
#define EMB_DIM  192                  // 3*H
#define OUT_DIM  10

// -------- scratch (static device globals; no runtime allocation) --------
__device__ float d_hA[NNODES * H];
__device__ float d_hB[NNODES * H];
__device__ float d_msg1[NNODES * H];

__device__ float d_h2A[N2 * H];
__device__ float d_h2B[N2 * H];
__device__ float d_msg2[N2 * H];

__device__ float d_h3A[N3 * H];
__device__ float d_h3B[N3 * H];
__device__ float d_msg3[N3 * H];

__device__ float d_emb[GG * EMB_DIM];

// ---------------- kernels ----------------

// Y1 = X @ W1^T ; MSG = X @ W2^T.  One block per row, 64 threads (one per out col).
__global__ void fused_lin(const float* __restrict__ X,
                          const float* __restrict__ W1,
                          const float* __restrict__ W2,
                          float* __restrict__ Y1, float* __restrict__ MSG,
                          int K) {
    extern __shared__ float xr[];
    int r = blockIdx.x;
    int j = threadIdx.x;
    const float* xrow = X + (size_t)r * K;
    for (int k = j; k < K; k += H) xr[k] = xrow[k];
    __syncthreads();
    float a1 = 0.f, a2 = 0.f;
    const float* __restrict__ w1 = W1 + j * K;
    const float* __restrict__ w2 = W2 + j * K;
#pragma unroll 4
    for (int k = 0; k < K; k++) {
        float v = xr[k];
        a1 += v * w1[k];
        a2 += v * w2[k];
    }
    Y1[(size_t)r * H + j]  = a1;
    MSG[(size_t)r * H + j] = a2;
}

// Level-2 layer 0: input row = [h[gu], h[gv], iso] (K=129)
__global__ void fused_lin_g2(const float* __restrict__ hsrc,
                             const int* __restrict__ gu, const int* __restrict__ gv,
                             const float* __restrict__ iso,
                             const float* __restrict__ W1, const float* __restrict__ W2,
                             float* __restrict__ Y1, float* __restrict__ MSG) {
    __shared__ float xr[129];
    int r = blockIdx.x;
    int j = threadIdx.x;
    int u = gu[r], v = gv[r];
    xr[j]      = hsrc[(size_t)u * H + j];
    xr[H + j]  = hsrc[(size_t)v * H + j];
    if (j == 0) xr[128] = iso[r];
    __syncthreads();
    float a1 = 0.f, a2 = 0.f;
    const float* __restrict__ w1 = W1 + j * 129;
    const float* __restrict__ w2 = W2 + j * 129;
#pragma unroll 4
    for (int k = 0; k < 129; k++) {
        float x = xr[k];
        a1 += x * w1[k];
        a2 += x * w2[k];
    }
    Y1[(size_t)r * H + j]  = a1;
    MSG[(size_t)r * H + j] = a2;
}

// Level-3 layer 0: input row = [h[ga], h[gb], h[gc], iso4] (K=196)
__global__ void fused_lin_g3(const float* __restrict__ hsrc,
                             const int* __restrict__ ga, const int* __restrict__ gb,
                             const int* __restrict__ gc,
                             const float* __restrict__ iso,
                             const float* __restrict__ W1, const float* __restrict__ W2,
                             float* __restrict__ Y1, float* __restrict__ MSG) {
    __shared__ float xr[196];
    int r = blockIdx.x;
    int j = threadIdx.x;
    int a = ga[r], b = gb[r], c = gc[r];
    xr[j]         = hsrc[(size_t)a * H + j];
    xr[H + j]     = hsrc[(size_t)b * H + j];
    xr[2 * H + j] = hsrc[(size_t)c * H + j];
    if (j < 4) xr[192 + j] = iso[(size_t)r * 4 + j];
    __syncthreads();
    float a1 = 0.f, a2 = 0.f;
    const float* __restrict__ w1 = W1 + j * 196;
    const float* __restrict__ w2 = W2 + j * 196;
#pragma unroll 4
    for (int k = 0; k < 196; k++) {
        float x = xr[k];
        a1 += x * w1[k];
        a2 += x * w2[k];
    }
    Y1[(size_t)r * H + j]  = a1;
    MSG[(size_t)r * H + j] = a2;
}

// out[dst[e]] += msg[src[e]]  (64 floats per edge, float4 chunks, 16 threads/edge)
__global__ void scatter_add(const float4* __restrict__ msg,
                            const int* __restrict__ src, const int* __restrict__ dst,
                            int E, float* __restrict__ out) {
    long long idx = (long long)blockIdx.x * blockDim.x + threadIdx.x;
    int e = (int)(idx >> 4);
    if (e >= E) return;
    int c4 = (int)(idx & 15);
    float4 v = msg[(size_t)src[e] * 16 + c4];
    float* o = out + (size_t)dst[e] * H + c4 * 4;
    atomicAdd(o + 0, v.x);
    atomicAdd(o + 1, v.y);
    atomicAdd(o + 2, v.z);
    atomicAdd(o + 3, v.w);
}

__global__ void relu_inplace(float* __restrict__ y, int n) {
    int i = blockIdx.x * blockDim.x + threadIdx.x;
    if (i < n) y[i] = fmaxf(y[i], 0.f);
}

// emb[g, colOff + c] = sum over rows-per-graph of Y (contiguous blocks).
__global__ void seg_reduce(const float* __restrict__ Y, int rpg,
                           float* __restrict__ emb, int colOff) {
    int g = blockIdx.x;
    int c = threadIdx.x;  // 64
    const float* base = Y + (size_t)g * rpg * H + c;
    float s = 0.f;
    for (int i = 0; i < rpg; i++) s += base[(size_t)i * H];
    emb[g * EMB_DIM + colOff + c] = s;
}

// hid = relu(emb@cW1^T + cb1); out = hid@cW2^T + cb2. One block per graph.
__global__ void head(const float* __restrict__ emb,
                     const float* __restrict__ cW1, const float* __restrict__ cb1,
                     const float* __restrict__ cW2, const float* __restrict__ cb2,
                     float* __restrict__ out) {
    __shared__ float e[EMB_DIM];
    __shared__ float hid[H];
    int g = blockIdx.x;
    int t = threadIdx.x;  // 64
    for (int k = t; k < EMB_DIM; k += H) e[k] = emb[g * EMB_DIM + k];
    __syncthreads();
    float a = cb1[t];
    const float* w = cW1 + t * EMB_DIM;
#pragma unroll 4
    for (int k = 0; k < EMB_DIM; k++) a += e[k] * w[k];
    hid[t] = fmaxf(a, 0.f);
    __syncthreads();
    if (t < OUT_DIM) {
        float a2 = cb2[t];
        const float* w2 = cW2 + t * H;
#pragma unroll 8
        for (int k = 0; k < H; k++) a2 += hid[k] * w2[k];
        out[g * OUT_DIM + t] = a2;
    }
}

// ---------------- launch ----------------

extern "C" void kernel_launch(void* const* d_in, const int* in_sizes, int n_in,
                              void* d_out, int out_size) {
    const float* x          = (const float*)d_in[0];
    const int*   edge_index = (const int*)d_in[1];
    // d_in[2] = batch (unused; level-1 rows are contiguous per graph)
    const int*   gu2        = (const int*)d_in[3];
    const int*   gv2        = (const int*)d_in[4];
    const float* iso2       = (const float*)d_in[5];
    const int*   two_edges  = (const int*)d_in[6];
    // d_in[7] = two_batch (unused)
    const int*   ga3        = (const int*)d_in[8];
    const int*   gb3        = (const int*)d_in[9];
    const int*   gc3        = (const int*)d_in[10];
    const float* iso3       = (const float*)d_in[11];
    const int*   three_edges= (const int*)d_in[12];
    // d_in[13] = three_batch (unused)
    const float* g1W1_0 = (const float*)d_in[14];
    const float* g1W2_0 = (const float*)d_in[15];
    const float* g1W1_1 = (const float*)d_in[16];
    const float* g1W2_1 = (const float*)d_in[17];
    const float* g1W1_2 = (const float*)d_in[18];
    const float* g1W2_2 = (const float*)d_in[19];
    const float* g2W1_0 = (const float*)d_in[20];
    const float* g2W2_0 = (const float*)d_in[21];
    const float* g2W1_1 = (const float*)d_in[22];
    const float* g2W2_1 = (const float*)d_in[23];
    const float* g3W1_0 = (const float*)d_in[24];
    const float* g3W2_0 = (const float*)d_in[25];
    const float* g3W1_1 = (const float*)d_in[26];
    const float* g3W2_1 = (const float*)d_in[27];
    const float* cW1    = (const float*)d_in[28];
    const float* cb1    = (const float*)d_in[29];
    const float* cW2    = (const float*)d_in[30];
    const float* cb2    = (const float*)d_in[31];
    float* out = (float*)d_out;

    const int E1 = in_sizes[1] / 2;
    const int E2 = in_sizes[6] / 2;
    const int E3 = in_sizes[12] / 2;

    float *hA, *hB, *msg1, *h2A, *h2B, *msg2, *h3A, *h3B, *msg3, *emb;
    cudaGetSymbolAddress((void**)&hA,  d_hA);
    cudaGetSymbolAddress((void**)&hB,  d_hB);
    cudaGetSymbolAddress((void**)&msg1,d_msg1);
    cudaGetSymbolAddress((void**)&h2A, d_h2A);
    cudaGetSymbolAddress((void**)&h2B, d_h2B);
    cudaGetSymbolAddress((void**)&msg2,d_msg2);
    cudaGetSymbolAddress((void**)&h3A, d_h3A);
    cudaGetSymbolAddress((void**)&h3B, d_h3B);
    cudaGetSymbolAddress((void**)&msg3,d_msg3);
    cudaGetSymbolAddress((void**)&emb, d_emb);

    const int T = H;  // 64 threads per row-block
    auto relu_grid = [](int n) { return (n + 255) / 256; };
    auto sc_grid   = [](int E) { return (int)(((long long)E * 16 + 255) / 256); };

    const int* e1s = edge_index;          const int* e1d = edge_index + E1;
    const int* e2s = two_edges;           const int* e2d = two_edges + E2;
    const int* e3s = three_edges;         const int* e3d = three_edges + E3;

    // ---- level 1 (3 layers) ----
    fused_lin<<<NNODES, T, 32 * sizeof(float)>>>(x, g1W1_0, g1W2_0, hA, msg1, 32);
    scatter_add<<<sc_grid(E1), 256>>>((const float4*)msg1, e1s, e1d, E1, hA);
    relu_inplace<<<relu_grid(NNODES * H), 256>>>(hA, NNODES * H);

    fused_lin<<<NNODES, T, H * sizeof(float)>>>(hA, g1W1_1, g1W2_1, hB, msg1, H);
    scatter_add<<<sc_grid(E1), 256>>>((const float4*)msg1, e1s, e1d, E1, hB);
    relu_inplace<<<relu_grid(NNODES * H), 256>>>(hB, NNODES * H);

    fused_lin<<<NNODES, T, H * sizeof(float)>>>(hB, g1W1_2, g1W2_2, hA, msg1, H);
    scatter_add<<<sc_grid(E1), 256>>>((const float4*)msg1, e1s, e1d, E1, hA);
    relu_inplace<<<relu_grid(NNODES * H), 256>>>(hA, NNODES * H);

    seg_reduce<<<GG, H>>>(hA, NPER, emb, 0);

    // ---- level 2 (2 layers) ----
    fused_lin_g2<<<N2, T>>>(hA, gu2, gv2, iso2, g2W1_0, g2W2_0, h2A, msg2);
    scatter_add<<<sc_grid(E2), 256>>>((const float4*)msg2, e2s, e2d, E2, h2A);
    relu_inplace<<<relu_grid(N2 * H), 256>>>(h2A, N2 * H);

    fused_lin<<<N2, T, H * sizeof(float)>>>(h2A, g2W1_1, g2W2_1, h2B, msg2, H);
    scatter_add<<<sc_grid(E2), 256>>>((const float4*)msg2, e2s, e2d, E2, h2B);
    relu_inplace<<<relu_grid(N2 * H), 256>>>(h2B, N2 * H);

    seg_reduce<<<GG, H>>>(h2B, P2, emb, H);

    // ---- level 3 (2 layers) ----
    fused_lin_g3<<<N3, T>>>(hA, ga3, gb3, gc3, iso3, g3W1_0, g3W2_0, h3A, msg3);
    scatter_add<<<sc_grid(E3), 256>>>((const float4*)msg3, e3s, e3d, E3, h3A);
    relu_inplace<<<relu_grid(N3 * H), 256>>>(h3A, N3 * H);

    fused_lin<<<N3, T, H * sizeof(float)>>>(h3A, g3W1_1, g3W2_1, h3B, msg3, H);
    scatter_add<<<sc_grid(E3), 256>>>((const float4*)msg3, e3s, e3d, E3, h3B);
    relu_inplace<<<relu_grid(N3 * H), 256>>>(h3B, N3 * H);

    seg_reduce<<<GG, H>>>(h3B, P3, emb, 2 * H);

    // ---- head ----
    head<<<GG, H>>>(emb, cW1, cb1, cW2, cb2, out);
}

// round 2
// speedup vs baseline: 17.1606x; 17.1606x over previous
#include <cuda_runtime.h>
#include <cstdint>

// Problem constants (fixed by reference _build_structures with seed 0)
#define GG       128
#define NPER     20
#define NNODES   (GG * NPER)          // 2560
#define P2       190
#define N2       (GG * P2)            // 24320
#define P3       1140
#define N3       (GG * P3)            // 145920
#define H        64
#define EMB_DIM  192
#define OUT_DIM  10

// -------- scratch (static device globals; no runtime allocation) --------
__device__ float d_hA[NNODES * H];
__device__ float d_hB[NNODES * H];
__device__ float d_msg1[NNODES * H];

__device__ float d_h2A[N2 * H];
__device__ float d_h2B[N2 * H];
__device__ float d_msg2[N2 * H];

__device__ float d_h3A[N3 * H];
__device__ float d_h3B[N3 * H];
__device__ float d_msg3[N3 * H];

__device__ float d_emb[GG * EMB_DIM];

// transposed fused weights: per layer Wt[k][j], j<64 -> W1 col, j>=64 -> W2 col
// k-row offsets: L1_0:0(32) L1_1:32(64) L1_2:96(64) G2_0:160(160) G2_1:320(64)
//                G3_0:384(224) G3_1:608(64)   total 672 k-rows
__device__ float d_Wt[672 * 128];

// ---------------- weight prep ----------------
struct WPrepAll {
    const float* w1[7];
    const float* w2[7];
    int K[7];
    int Kpad[7];
    int off[7];
};

__global__ void prep_weights(WPrepAll P, float* __restrict__ Wt) {
    int l = blockIdx.x;
    const float* __restrict__ w1 = P.w1[l];
    const float* __restrict__ w2 = P.w2[l];
    int K = P.K[l], KP = P.Kpad[l];
    float* out = Wt + (size_t)P.off[l] * 128;
    for (int i = threadIdx.x; i < KP * 128; i += blockDim.x) {
        int k = i >> 7, j = i & 127;
        float v = 0.f;
        if (k < K) v = (j < 64) ? w1[j * K + k] : w2[(j - 64) * K + k];
        out[i] = v;
    }
}

// ---------------- fused dual GEMM ----------------
// Y1 = act(X) @ W1^T ; MSG = act(X) @ W2^T  for a 64-row tile, 128 output cols.
// MODE 0: X rows contiguous (K == KPAD).
// MODE 2: row = [relu(h[ia]), relu(h[ib]), iso1]  (K=129, KPAD=160)
// MODE 3: row = [relu(h[ia]), relu(h[ib]), relu(h[ic]), iso4] (K=196, KPAD=224)
template <int KPAD, int MODE>
__global__ void __launch_bounds__(256)
gemm_dual(const float* __restrict__ Xsrc,
          const int* __restrict__ ia, const int* __restrict__ ib,
          const int* __restrict__ ic,
          const float* __restrict__ iso,
          const float* __restrict__ Wt,
          float* __restrict__ Y1, float* __restrict__ MSG,
          int reluIn) {
    extern __shared__ float sm[];
    float* Xs  = sm;                  // [64][KPAD]
    float* Wsh = sm + 64 * KPAD;      // [32][128]
    const int t = threadIdx.x;
    const int rowBase = blockIdx.x * 64;

    // ---- stage X tile ----
    if (MODE == 0) {
        const float4* src = (const float4*)(Xsrc + (size_t)rowBase * KPAD);
        float4* dst = (float4*)Xs;
        const int n4 = 64 * KPAD / 4;
        for (int i = t; i < n4; i += 256) {
            float4 v = src[i];
            if (reluIn) {
                v.x = fmaxf(v.x, 0.f); v.y = fmaxf(v.y, 0.f);
                v.z = fmaxf(v.z, 0.f); v.w = fmaxf(v.w, 0.f);
            }
            dst[i] = v;
        }
    } else {
        const int r = t >> 2, q = t & 3;
        const int nseg = (MODE == 2) ? 2 : 3;
#pragma unroll
        for (int seg = 0; seg < nseg; seg++) {
            const int* idxp = (seg == 0) ? ia : (seg == 1) ? ib : ic;
            int srcRow = idxp[rowBase + r];
            const float4* src = (const float4*)(Xsrc + (size_t)srcRow * 64);
            float4* dst = (float4*)(Xs + r * KPAD + seg * 64);
#pragma unroll
            for (int i = 0; i < 4; i++) {
                float4 v = src[q * 4 + i];
                v.x = fmaxf(v.x, 0.f); v.y = fmaxf(v.y, 0.f);
                v.z = fmaxf(v.z, 0.f); v.w = fmaxf(v.w, 0.f);
                dst[q * 4 + i] = v;
            }
        }
        if (t < 64) {
            if (MODE == 2) {
                Xs[t * KPAD + 128] = iso[rowBase + t];
#pragma unroll
                for (int k = 129; k < KPAD; k++) Xs[t * KPAD + k] = 0.f;
            } else {
                float4 v = ((const float4*)iso)[rowBase + t];
                *(float4*)(Xs + t * KPAD + 192) = v;
#pragma unroll
                for (int k = 196; k < KPAD; k++) Xs[t * KPAD + k] = 0.f;
            }
        }
    }

    // ---- compute: 8 rows x 4 cols per thread ----
    const int cg = t & 31;   // col group (4 cols)
    const int rg = t >> 5;   // row group (8 rows)
    float acc[8][4];
#pragma unroll
    for (int r = 0; r < 8; r++) {
        acc[r][0] = acc[r][1] = acc[r][2] = acc[r][3] = 0.f;
    }
    const float* Xw = Xs + rg * 8 * KPAD;

    for (int k0 = 0; k0 < KPAD; k0 += 32) {
        __syncthreads();
        {
            const float4* s4 = (const float4*)(Wt + (size_t)k0 * 128);
            float4* d4 = (float4*)Wsh;
#pragma unroll
            for (int i = 0; i < 4; i++) d4[t + i * 256] = s4[t + i * 256];
        }
        __syncthreads();
#pragma unroll
        for (int kk = 0; kk < 32; kk++) {
            float4 w = *(const float4*)(Wsh + kk * 128 + cg * 4);
#pragma unroll
            for (int r = 0; r < 8; r++) {
                float xv = Xw[r * KPAD + k0 + kk];
                acc[r][0] += xv * w.x;
                acc[r][1] += xv * w.y;
                acc[r][2] += xv * w.z;
                acc[r][3] += xv * w.w;
            }
        }
    }

    // ---- epilogue ----
    float* outp = (cg < 16)
        ? (Y1  + (size_t)(rowBase + rg * 8) * 64 + cg * 4)
        : (MSG + (size_t)(rowBase + rg * 8) * 64 + (cg - 16) * 4);
#pragma unroll
    for (int r = 0; r < 8; r++) {
        float4 v;
        v.x = acc[r][0]; v.y = acc[r][1]; v.z = acc[r][2]; v.w = acc[r][3];
        *(float4*)(outp + (size_t)r * 64) = v;
    }
}

// ---------------- scatter: out[dst[e]] += msg[src[e]] (64 floats/edge) ----
__global__ void scatter_add(const float4* __restrict__ msg,
                            const int* __restrict__ src,
                            const int* __restrict__ dst,
                            int E, float* __restrict__ out) {
    long long idx = (long long)blockIdx.x * blockDim.x + threadIdx.x;
    int e = (int)(idx >> 4);
    if (e >= E) return;
    int c = (int)(idx & 15);
    float4 v = msg[(size_t)src[e] * 16 + c];
    float* o = out + (size_t)dst[e] * 64 + c * 4;
    asm volatile("red.global.add.v4.f32 [%0], {%1,%2,%3,%4};"
                 :: "l"(o), "f"(v.x), "f"(v.y), "f"(v.z), "f"(v.w)
                 : "memory");
}

// ---------------- per-graph column sum with fused relu ----------------
__global__ void seg_reduce(const float* __restrict__ Y, int rpg,
                           float* __restrict__ emb, int colOff) {
    __shared__ float partial[4][64];
    int g = blockIdx.x;
    int c = threadIdx.x & 63;
    int s = threadIdx.x >> 6;
    const float* base = Y + (size_t)g * rpg * 64 + c;
    float sum = 0.f;
    for (int i = s; i < rpg; i += 4) sum += fmaxf(base[(size_t)i * 64], 0.f);
    partial[s][c] = sum;
    __syncthreads();
    if (s == 0)
        emb[g * EMB_DIM + colOff + c] =
            partial[0][c] + partial[1][c] + partial[2][c] + partial[3][c];
}

// ---------------- classifier head ----------------
__global__ void head(const float* __restrict__ emb,
                     const float* __restrict__ cW1, const float* __restrict__ cb1,
                     const float* __restrict__ cW2, const float* __restrict__ cb2,
                     float* __restrict__ out) {
    __shared__ float e[EMB_DIM];
    __shared__ float hid[H];
    int g = blockIdx.x;
    int t = threadIdx.x;  // 64
    for (int k = t; k < EMB_DIM; k += H) e[k] = emb[g * EMB_DIM + k];
    __syncthreads();
    float a = cb1[t];
    const float* w = cW1 + t * EMB_DIM;
#pragma unroll 4
    for (int k = 0; k < EMB_DIM; k++) a += e[k] * w[k];
    hid[t] = fmaxf(a, 0.f);
    __syncthreads();
    if (t < OUT_DIM) {
        float a2 = cb2[t];
        const float* w2 = cW2 + t * H;
#pragma unroll 8
        for (int k = 0; k < H; k++) a2 += hid[k] * w2[k];
        out[g * OUT_DIM + t] = a2;
    }
}

// ---------------- launch ----------------
extern "C" void kernel_launch(void* const* d_in, const int* in_sizes, int n_in,
                              void* d_out, int out_size) {
    const float* x           = (const float*)d_in[0];
    const int*   edge_index  = (const int*)d_in[1];
    const int*   gu2         = (const int*)d_in[3];
    const int*   gv2         = (const int*)d_in[4];
    const float* iso2        = (const float*)d_in[5];
    const int*   two_edges   = (const int*)d_in[6];
    const int*   ga3         = (const int*)d_in[8];
    const int*   gb3         = (const int*)d_in[9];
    const int*   gc3         = (const int*)d_in[10];
    const float* iso3        = (const float*)d_in[11];
    const int*   three_edges = (const int*)d_in[12];
    const float* g1W1_0 = (const float*)d_in[14];
    const float* g1W2_0 = (const float*)d_in[15];
    const float* g1W1_1 = (const float*)d_in[16];
    const float* g1W2_1 = (const float*)d_in[17];
    const float* g1W1_2 = (const float*)d_in[18];
    const float* g1W2_2 = (const float*)d_in[19];
    const float* g2W1_0 = (const float*)d_in[20];
    const float* g2W2_0 = (const float*)d_in[21];
    const float* g2W1_1 = (const float*)d_in[22];
    const float* g2W2_1 = (const float*)d_in[23];
    const float* g3W1_0 = (const float*)d_in[24];
    const float* g3W2_0 = (const float*)d_in[25];
    const float* g3W1_1 = (const float*)d_in[26];
    const float* g3W2_1 = (const float*)d_in[27];
    const float* cW1    = (const float*)d_in[28];
    const float* cb1    = (const float*)d_in[29];
    const float* cW2    = (const float*)d_in[30];
    const float* cb2    = (const float*)d_in[31];
    float* out = (float*)d_out;

    const int E1 = in_sizes[1] / 2;
    const int E2 = in_sizes[6] / 2;
    const int E3 = in_sizes[12] / 2;

    float *hA, *hB, *msg1, *h2A, *h2B, *msg2, *h3A, *h3B, *msg3, *emb, *Wt;
    cudaGetSymbolAddress((void**)&hA,   d_hA);
    cudaGetSymbolAddress((void**)&hB,   d_hB);
    cudaGetSymbolAddress((void**)&msg1, d_msg1);
    cudaGetSymbolAddress((void**)&h2A,  d_h2A);
    cudaGetSymbolAddress((void**)&h2B,  d_h2B);
    cudaGetSymbolAddress((void**)&msg2, d_msg2);
    cudaGetSymbolAddress((void**)&h3A,  d_h3A);
    cudaGetSymbolAddress((void**)&h3B,  d_h3B);
    cudaGetSymbolAddress((void**)&msg3, d_msg3);
    cudaGetSymbolAddress((void**)&emb,  d_emb);
    cudaGetSymbolAddress((void**)&Wt,   d_Wt);

    // opt-in for >48KB dynamic smem instances (idempotent, capture-safe)
    cudaFuncSetAttribute((const void*)gemm_dual<224, 3>,
                         cudaFuncAttributeMaxDynamicSharedMemorySize, 73728);
    cudaFuncSetAttribute((const void*)gemm_dual<160, 2>,
                         cudaFuncAttributeMaxDynamicSharedMemorySize, 57344);

    // ---- weight prep ----
    WPrepAll P;
    P.w1[0] = g1W1_0; P.w2[0] = g1W2_0; P.K[0] = 32;  P.Kpad[0] = 32;  P.off[0] = 0;
    P.w1[1] = g1W1_1; P.w2[1] = g1W2_1; P.K[1] = 64;  P.Kpad[1] = 64;  P.off[1] = 32;
    P.w1[2] = g1W1_2; P.w2[2] = g1W2_2; P.K[2] = 64;  P.Kpad[2] = 64;  P.off[2] = 96;
    P.w1[3] = g2W1_0; P.w2[3] = g2W2_0; P.K[3] = 129; P.Kpad[3] = 160; P.off[3] = 160;
    P.w1[4] = g2W1_1; P.w2[4] = g2W2_1; P.K[4] = 64;  P.Kpad[4] = 64;  P.off[4] = 320;
    P.w1[5] = g3W1_0; P.w2[5] = g3W2_0; P.K[5] = 196; P.Kpad[5] = 224; P.off[5] = 384;
    P.w1[6] = g3W1_1; P.w2[6] = g3W2_1; P.K[6] = 64;  P.Kpad[6] = 64;  P.off[6] = 608;
    prep_weights<<<7, 256>>>(P, Wt);

    const int* e1s = edge_index;  const int* e1d = edge_index + E1;
    const int* e2s = two_edges;   const int* e2d = two_edges + E2;
    const int* e3s = three_edges; const int* e3d = three_edges + E3;

    auto sc_grid = [](int E) { return (int)(((long long)E * 16 + 255) / 256); };

    const size_t sm32  = (64 * 32  + 32 * 128) * 4;
    const size_t sm64  = (64 * 64  + 32 * 128) * 4;
    const size_t sm160 = (64 * 160 + 32 * 128) * 4;
    const size_t sm224 = (64 * 224 + 32 * 128) * 4;

    // ---- level 1 (3 layers); h buffers hold PRE-activation, relu fused in consumers
    gemm_dual<32, 0><<<NNODES / 64, 256, sm32>>>(x, nullptr, nullptr, nullptr, nullptr,
                                                 Wt + 0 * 128, hA, msg1, 0);
    scatter_add<<<sc_grid(E1), 256>>>((const float4*)msg1, e1s, e1d, E1, hA);

    gemm_dual<64, 0><<<NNODES / 64, 256, sm64>>>(hA, nullptr, nullptr, nullptr, nullptr,
                                                 Wt + 32 * 128, hB, msg1, 1);
    scatter_add<<<sc_grid(E1), 256>>>((const float4*)msg1, e1s, e1d, E1, hB);

    gemm_dual<64, 0><<<NNODES / 64, 256, sm64>>>(hB, nullptr, nullptr, nullptr, nullptr,
                                                 Wt + 96 * 128, hA, msg1, 1);
    scatter_add<<<sc_grid(E1), 256>>>((const float4*)msg1, e1s, e1d, E1, hA);

    seg_reduce<<<GG, 256>>>(hA, NPER, emb, 0);

    // ---- level 2 (2 layers) ----
    gemm_dual<160, 2><<<N2 / 64, 256, sm160>>>(hA, gu2, gv2, nullptr, iso2,
                                               Wt + 160 * 128, h2A, msg2, 1);
    scatter_add<<<sc_grid(E2), 256>>>((const float4*)msg2, e2s, e2d, E2, h2A);

    gemm_dual<64, 0><<<N2 / 64, 256, sm64>>>(h2A, nullptr, nullptr, nullptr, nullptr,
                                             Wt + 320 * 128, h2B, msg2, 1);
    scatter_add<<<sc_grid(E2), 256>>>((const float4*)msg2, e2s, e2d, E2, h2B);

    seg_reduce<<<GG, 256>>>(h2B, P2, emb, H);

    // ---- level 3 (2 layers) ----
    gemm_dual<224, 3><<<N3 / 64, 256, sm224>>>(hA, ga3, gb3, gc3, iso3,
                                               Wt + 384 * 128, h3A, msg3, 1);
    scatter_add<<<sc_grid(E3), 256>>>((const float4*)msg3, e3s, e3d, E3, h3A);

    gemm_dual<64, 0><<<N3 / 64, 256, sm64>>>(h3A, nullptr, nullptr, nullptr, nullptr,
                                             Wt + 608 * 128, h3B, msg3, 1);
    scatter_add<<<sc_grid(E3), 256>>>((const float4*)msg3, e3s, e3d, E3, h3B);

    seg_reduce<<<GG, 256>>>(h3B, P3, emb, 2 * H);

    // ---- head ----
    head<<<GG, H>>>(emb, cW1, cb1, cW2, cb2, out);
}

// round 5
// speedup vs baseline: 18.9568x; 1.1047x over previous
#include <cuda_runtime.h>
#include <cstdint>

// Problem constants (fixed by reference _build_structures with seed 0)
#define GG       128
#define NPER     20
#define NNODES   (GG * NPER)          // 2560
#define P2       190
#define N2       (GG * P2)            // 24320
#define P3       1140
#define N3       (GG * P3)            // 145920
#define H        64
#define EMB_DIM  192
#define OUT_DIM  10

// -------- scratch (static device globals; no runtime allocation) --------
__device__ float d_hA[NNODES * H];
__device__ float d_hB[NNODES * H];
__device__ float d_msg1[NNODES * H];

__device__ float d_h2A[N2 * H];
__device__ float d_h2B[N2 * H];
__device__ float d_msg2[N2 * H];

__device__ float d_h3A[N3 * H];
__device__ float d_h3B[N3 * H];
__device__ float d_msg3[N3 * H];

__device__ float d_emb[GG * EMB_DIM];

// transposed fused weights for the FFMA path (level 1 only)
// offsets: L1_0:0(32) L1_1:32(64) L1_2:96(64)
__device__ float d_Wt[160 * 128];

// ============================================================
// helpers
// ============================================================
__device__ __forceinline__ uint32_t f2tf32(float f) {
    uint32_t u;
    asm("cvt.rna.tf32.f32 %0, %1;" : "=r"(u) : "f"(f));
    return u;
}
__device__ __forceinline__ uint32_t f2tf32_relu(float f) {
    return f2tf32(fmaxf(f, 0.f));
}
__device__ __forceinline__ void mma_tf32(float* c, const uint32_t* a, const uint32_t* b) {
    asm volatile(
        "mma.sync.aligned.m16n8k8.row.col.f32.tf32.tf32.f32 "
        "{%0,%1,%2,%3}, {%4,%5,%6,%7}, {%8,%9}, {%0,%1,%2,%3};"
        : "+f"(c[0]), "+f"(c[1]), "+f"(c[2]), "+f"(c[3])
        : "r"(a[0]), "r"(a[1]), "r"(a[2]), "r"(a[3]), "r"(b[0]), "r"(b[1]));
}

// ============================================================
// tf32 mma.sync dual GEMM: Y1||MSG = act(A) @ [W1^T | W2^T]
// Block tile: 128 rows x 128 cols, 8 warps (warp tile 32x64).
// A smem [128][K+4]  (stride K+4 == 4 mod 32 -> conflict-free A frags)
// B smem [K][136]    (136 == 8 mod 32       -> conflict-free B frags)
// MODE 0: contiguous rows (X stride = K), optional relu on input.
// MODE 2: row = [relu(h[ia]), relu(h[ib])], K=128; iso scalar added in epilogue.
// MODE 3: row = [relu(h[ia]), relu(h[ib]), relu(h[ic])], K=192; iso one-hot
//         contribution added in epilogue from 128x4 table (W cols K..K+3).
// ============================================================
template <int K, int MODE>
__global__ void __launch_bounds__(256)
gemm_mma(const float* __restrict__ X,
         const int* __restrict__ ia, const int* __restrict__ ib,
         const int* __restrict__ ic,
         const float* __restrict__ iso,
         const float* __restrict__ Wa, const float* __restrict__ Wb, int wK,
         float* __restrict__ Y1, float* __restrict__ MSG, int reluIn) {
    extern __shared__ float sm[];
    constexpr int SA = K + 4;
    float* As   = sm;                    // [128][SA]
    float* Bs   = sm + 128 * SA;         // [K][136]
    float* isoT = Bs + K * 136;          // MODE3: [128][4] ; MODE2: [128]

    const int t = threadIdx.x;
    const int rowBase = blockIdx.x * 128;

    // ---- stage B (tf32 convert). float4 row reads only when wK is a
    //      multiple of 4 (wK=129 rows are NOT 16B-aligned for odd j). ----
    {
        constexpr int K4 = K / 4;
        const bool vec4 = ((wK & 3) == 0);
        for (int i = t; i < 128 * K4; i += 256) {
            int j = i / K4;
            int k = (i - j * K4) * 4;
            const float* src = (j < 64) ? (Wa + (size_t)j * wK)
                                        : (Wb + (size_t)(j - 64) * wK);
            float4 v;
            if (vec4) {
                v = *(const float4*)(src + k);
            } else {
                v.x = src[k]; v.y = src[k + 1]; v.z = src[k + 2]; v.w = src[k + 3];
            }
            Bs[(k + 0) * 136 + j] = __uint_as_float(f2tf32(v.x));
            Bs[(k + 1) * 136 + j] = __uint_as_float(f2tf32(v.y));
            Bs[(k + 2) * 136 + j] = __uint_as_float(f2tf32(v.z));
            Bs[(k + 3) * 136 + j] = __uint_as_float(f2tf32(v.w));
        }
        if (MODE == 3) {
            for (int i = t; i < 512; i += 256) {
                int j = i >> 2, e = i & 3;
                const float* src = (j < 64) ? (Wa + (size_t)j * wK)
                                            : (Wb + (size_t)(j - 64) * wK);
                isoT[j * 4 + e] = src[K + e];
            }
        } else if (MODE == 2) {
            if (t < 128) {
                const float* src = (t < 64) ? (Wa + (size_t)t * wK)
                                            : (Wb + (size_t)(t - 64) * wK);
                isoT[t] = src[K];
            }
        }
    }

    // ---- stage A (relu + tf32) ----
    if (MODE == 0) {
        constexpr int K4 = K / 4;
        for (int i = t; i < 128 * K4; i += 256) {
            int row = i / K4;
            int k = (i - row * K4) * 4;
            float4 v = *(const float4*)(X + (size_t)(rowBase + row) * K + k);
            uint4 u;
            if (reluIn) {
                u.x = f2tf32_relu(v.x); u.y = f2tf32_relu(v.y);
                u.z = f2tf32_relu(v.z); u.w = f2tf32_relu(v.w);
            } else {
                u.x = f2tf32(v.x); u.y = f2tf32(v.y);
                u.z = f2tf32(v.z); u.w = f2tf32(v.w);
            }
            *(uint4*)(As + row * SA + k) = u;
        }
    } else {
        const int r = t >> 1, half = t & 1;
        const int nseg = (MODE == 2) ? 2 : 3;
#pragma unroll
        for (int seg = 0; seg < nseg; seg++) {
            const int* idxp = (seg == 0) ? ia : (seg == 1) ? ib : ic;
            int srcRow = idxp[rowBase + r];
            const float4* src = (const float4*)(X + (size_t)srcRow * 64) + half * 8;
#pragma unroll
            for (int i = 0; i < 8; i++) {
                float4 v = src[i];
                uint4 u;
                u.x = f2tf32_relu(v.x); u.y = f2tf32_relu(v.y);
                u.z = f2tf32_relu(v.z); u.w = f2tf32_relu(v.w);
                *(uint4*)(As + r * SA + seg * 64 + half * 32 + i * 4) = u;
            }
        }
    }
    __syncthreads();

    // ---- compute ----
    const int lane = t & 31;
    const int wid = t >> 5;
    const int wm = (wid & 3) * 32;       // warp row offset
    const int wn = (wid >> 2) * 64;      // warp col offset (0 -> Y1, 64 -> MSG)
    const int ar = lane >> 2, ak = lane & 3;
    const int bc = lane >> 2, bk = lane & 3;

    float acc[2][8][4];
#pragma unroll
    for (int mt = 0; mt < 2; mt++)
#pragma unroll
        for (int nt = 0; nt < 8; nt++) {
            acc[mt][nt][0] = 0.f; acc[mt][nt][1] = 0.f;
            acc[mt][nt][2] = 0.f; acc[mt][nt][3] = 0.f;
        }

#pragma unroll 2
    for (int k0 = 0; k0 < K; k0 += 8) {
        uint32_t af[2][4];
#pragma unroll
        for (int mt = 0; mt < 2; mt++) {
            const float* p = As + (wm + mt * 16 + ar) * SA + k0 + ak;
            af[mt][0] = __float_as_uint(p[0]);
            af[mt][1] = __float_as_uint(p[8 * SA]);
            af[mt][2] = __float_as_uint(p[4]);
            af[mt][3] = __float_as_uint(p[8 * SA + 4]);
        }
        uint32_t bf[8][2];
#pragma unroll
        for (int nt = 0; nt < 8; nt++) {
            const float* p = Bs + (k0 + bk) * 136 + wn + nt * 8 + bc;
            bf[nt][0] = __float_as_uint(p[0]);
            bf[nt][1] = __float_as_uint(p[4 * 136]);
        }
#pragma unroll
        for (int mt = 0; mt < 2; mt++)
#pragma unroll
            for (int nt = 0; nt < 8; nt++)
                mma_tf32(acc[mt][nt], af[mt], bf[nt]);
    }

    // ---- epilogue ----
    float* dstBase = (wid >> 2) ? MSG : Y1;
#pragma unroll
    for (int mt = 0; mt < 2; mt++) {
        int r0 = rowBase + wm + mt * 16 + (lane >> 2);
        int r1 = r0 + 8;
        int e0 = 0, e1 = 0;
        float s0 = 0.f, s1 = 0.f;
        if (MODE == 3) {
            float4 v0 = ((const float4*)iso)[r0];
            float4 v1 = ((const float4*)iso)[r1];
            e0 = (int)(v0.y + 2.f * v0.z + 3.f * v0.w + 0.5f);
            e1 = (int)(v1.y + 2.f * v1.z + 3.f * v1.w + 0.5f);
        } else if (MODE == 2) {
            s0 = iso[r0];
            s1 = iso[r1];
        }
        float* d0 = dstBase + (size_t)r0 * 64;
        float* d1 = dstBase + (size_t)r1 * 64;
#pragma unroll
        for (int nt = 0; nt < 8; nt++) {
            int gc = wn + nt * 8 + 2 * (lane & 3);  // global col 0..127
            int oc = gc & 63;                        // col within output half
            float v0 = acc[mt][nt][0], v1 = acc[mt][nt][1];
            float v2 = acc[mt][nt][2], v3 = acc[mt][nt][3];
            if (MODE == 3) {
                v0 += isoT[gc * 4 + e0];       v1 += isoT[(gc + 1) * 4 + e0];
                v2 += isoT[gc * 4 + e1];       v3 += isoT[(gc + 1) * 4 + e1];
            } else if (MODE == 2) {
                v0 += s0 * isoT[gc];           v1 += s0 * isoT[gc + 1];
                v2 += s1 * isoT[gc];           v3 += s1 * isoT[gc + 1];
            }
            *(float2*)(d0 + oc) = make_float2(v0, v1);
            *(float2*)(d1 + oc) = make_float2(v2, v3);
        }
    }
}

// ============================================================
// FFMA path (level 1) — unchanged from the verified R2 kernel
// ============================================================
struct WPrepAll {
    const float* w1[3];
    const float* w2[3];
    int K[3];
    int off[3];
};

__global__ void prep_weights(WPrepAll P, float* __restrict__ Wt) {
    int l = blockIdx.x;
    const float* __restrict__ w1 = P.w1[l];
    const float* __restrict__ w2 = P.w2[l];
    int K = P.K[l];
    float* out = Wt + (size_t)P.off[l] * 128;
    for (int i = threadIdx.x; i < K * 128; i += blockDim.x) {
        int k = i >> 7, j = i & 127;
        out[i] = (j < 64) ? w1[j * K + k] : w2[(j - 64) * K + k];
    }
}

template <int KPAD>
__global__ void __launch_bounds__(256)
gemm_dual(const float* __restrict__ Xsrc,
          const float* __restrict__ Wt,
          float* __restrict__ Y1, float* __restrict__ MSG,
          int reluIn) {
    extern __shared__ float smf[];
    float* Xs  = smf;
    float* Wsh = smf + 64 * KPAD;
    const int t = threadIdx.x;
    const int rowBase = blockIdx.x * 64;

    {
        const float4* src = (const float4*)(Xsrc + (size_t)rowBase * KPAD);
        float4* dst = (float4*)Xs;
        const int n4 = 64 * KPAD / 4;
        for (int i = t; i < n4; i += 256) {
            float4 v = src[i];
            if (reluIn) {
                v.x = fmaxf(v.x, 0.f); v.y = fmaxf(v.y, 0.f);
                v.z = fmaxf(v.z, 0.f); v.w = fmaxf(v.w, 0.f);
            }
            dst[i] = v;
        }
    }

    const int cg = t & 31;
    const int rg = t >> 5;
    float acc[8][4];
#pragma unroll
    for (int r = 0; r < 8; r++) {
        acc[r][0] = acc[r][1] = acc[r][2] = acc[r][3] = 0.f;
    }
    const float* Xw = Xs + rg * 8 * KPAD;

    for (int k0 = 0; k0 < KPAD; k0 += 32) {
        __syncthreads();
        {
            const float4* s4 = (const float4*)(Wt + (size_t)k0 * 128);
            float4* d4 = (float4*)Wsh;
#pragma unroll
            for (int i = 0; i < 4; i++) d4[t + i * 256] = s4[t + i * 256];
        }
        __syncthreads();
#pragma unroll
        for (int kk = 0; kk < 32; kk++) {
            float4 wv = *(const float4*)(Wsh + kk * 128 + cg * 4);
#pragma unroll
            for (int r = 0; r < 8; r++) {
                float xv = Xw[r * KPAD + k0 + kk];
                acc[r][0] += xv * wv.x;
                acc[r][1] += xv * wv.y;
                acc[r][2] += xv * wv.z;
                acc[r][3] += xv * wv.w;
            }
        }
    }

    float* outp = (cg < 16)
        ? (Y1  + (size_t)(rowBase + rg * 8) * 64 + cg * 4)
        : (MSG + (size_t)(rowBase + rg * 8) * 64 + (cg - 16) * 4);
#pragma unroll
    for (int r = 0; r < 8; r++) {
        float4 v;
        v.x = acc[r][0]; v.y = acc[r][1]; v.z = acc[r][2]; v.w = acc[r][3];
        *(float4*)(outp + (size_t)r * 64) = v;
    }
}

// ---------------- scatter: out[dst[e]] += msg[src[e]] (64 floats/edge) ----
__global__ void scatter_add(const float4* __restrict__ msg,
                            const int* __restrict__ src,
                            const int* __restrict__ dst,
                            int E, float* __restrict__ out) {
    long long idx = (long long)blockIdx.x * blockDim.x + threadIdx.x;
    int e = (int)(idx >> 4);
    if (e >= E) return;
    int c = (int)(idx & 15);
    float4 v = msg[(size_t)src[e] * 16 + c];
    float* o = out + (size_t)dst[e] * 64 + c * 4;
    asm volatile("red.global.add.v4.f32 [%0], {%1,%2,%3,%4};"
                 :: "l"(o), "f"(v.x), "f"(v.y), "f"(v.z), "f"(v.w)
                 : "memory");
}

// ---------------- per-graph column sum with fused relu ----------------
__global__ void seg_reduce(const float* __restrict__ Y, int rpg,
                           float* __restrict__ emb, int colOff) {
    __shared__ float partial[4][64];
    int g = blockIdx.x;
    int c = threadIdx.x & 63;
    int s = threadIdx.x >> 6;
    const float* base = Y + (size_t)g * rpg * 64 + c;
    float sum = 0.f;
    for (int i = s; i < rpg; i += 4) sum += fmaxf(base[(size_t)i * 64], 0.f);
    partial[s][c] = sum;
    __syncthreads();
    if (s == 0)
        emb[g * EMB_DIM + colOff + c] =
            partial[0][c] + partial[1][c] + partial[2][c] + partial[3][c];
}

// ---------------- classifier head ----------------
__global__ void head(const float* __restrict__ emb,
                     const float* __restrict__ cW1, const float* __restrict__ cb1,
                     const float* __restrict__ cW2, const float* __restrict__ cb2,
                     float* __restrict__ out) {
    __shared__ float e[EMB_DIM];
    __shared__ float hid[H];
    int g = blockIdx.x;
    int t = threadIdx.x;
    for (int k = t; k < EMB_DIM; k += H) e[k] = emb[g * EMB_DIM + k];
    __syncthreads();
    float a = cb1[t];
    const float* w = cW1 + t * EMB_DIM;
#pragma unroll 4
    for (int k = 0; k < EMB_DIM; k++) a += e[k] * w[k];
    hid[t] = fmaxf(a, 0.f);
    __syncthreads();
    if (t < OUT_DIM) {
        float a2 = cb2[t];
        const float* w2 = cW2 + t * H;
#pragma unroll 8
        for (int k = 0; k < H; k++) a2 += hid[k] * w2[k];
        out[g * OUT_DIM + t] = a2;
    }
}

// ---------------- launch ----------------
extern "C" void kernel_launch(void* const* d_in, const int* in_sizes, int n_in,
                              void* d_out, int out_size) {
    const float* x           = (const float*)d_in[0];
    const int*   edge_index  = (const int*)d_in[1];
    const int*   gu2         = (const int*)d_in[3];
    const int*   gv2         = (const int*)d_in[4];
    const float* iso2        = (const float*)d_in[5];
    const int*   two_edges   = (const int*)d_in[6];
    const int*   ga3         = (const int*)d_in[8];
    const int*   gb3         = (const int*)d_in[9];
    const int*   gc3         = (const int*)d_in[10];
    const float* iso3        = (const float*)d_in[11];
    const int*   three_edges = (const int*)d_in[12];
    const float* g1W1_0 = (const float*)d_in[14];
    const float* g1W2_0 = (const float*)d_in[15];
    const float* g1W1_1 = (const float*)d_in[16];
    const float* g1W2_1 = (const float*)d_in[17];
    const float* g1W1_2 = (const float*)d_in[18];
    const float* g1W2_2 = (const float*)d_in[19];
    const float* g2W1_0 = (const float*)d_in[20];
    const float* g2W2_0 = (const float*)d_in[21];
    const float* g2W1_1 = (const float*)d_in[22];
    const float* g2W2_1 = (const float*)d_in[23];
    const float* g3W1_0 = (const float*)d_in[24];
    const float* g3W2_0 = (const float*)d_in[25];
    const float* g3W1_1 = (const float*)d_in[26];
    const float* g3W2_1 = (const float*)d_in[27];
    const float* cW1    = (const float*)d_in[28];
    const float* cb1    = (const float*)d_in[29];
    const float* cW2    = (const float*)d_in[30];
    const float* cb2    = (const float*)d_in[31];
    float* out = (float*)d_out;

    const int E1 = in_sizes[1] / 2;
    const int E2 = in_sizes[6] / 2;
    const int E3 = in_sizes[12] / 2;

    float *hA, *hB, *msg1, *h2A, *h2B, *msg2, *h3A, *h3B, *msg3, *emb, *Wt;
    cudaGetSymbolAddress((void**)&hA,   d_hA);
    cudaGetSymbolAddress((void**)&hB,   d_hB);
    cudaGetSymbolAddress((void**)&msg1, d_msg1);
    cudaGetSymbolAddress((void**)&h2A,  d_h2A);
    cudaGetSymbolAddress((void**)&h2B,  d_h2B);
    cudaGetSymbolAddress((void**)&msg2, d_msg2);
    cudaGetSymbolAddress((void**)&h3A,  d_h3A);
    cudaGetSymbolAddress((void**)&h3B,  d_h3B);
    cudaGetSymbolAddress((void**)&msg3, d_msg3);
    cudaGetSymbolAddress((void**)&emb,  d_emb);
    cudaGetSymbolAddress((void**)&Wt,   d_Wt);

    // dynamic smem sizes for mma instances
    const int SM_K192 = (128 * 196 + 192 * 136 + 512) * 4;  // 206848
    const int SM_K128 = (128 * 132 + 128 * 136 + 128) * 4;  // 137728
    const int SM_K64  = (128 * 68  + 64  * 136) * 4;        // 69632
    cudaFuncSetAttribute((const void*)gemm_mma<192, 3>,
                         cudaFuncAttributeMaxDynamicSharedMemorySize, SM_K192);
    cudaFuncSetAttribute((const void*)gemm_mma<128, 2>,
                         cudaFuncAttributeMaxDynamicSharedMemorySize, SM_K128);
    cudaFuncSetAttribute((const void*)gemm_mma<64, 0>,
                         cudaFuncAttributeMaxDynamicSharedMemorySize, SM_K64);

    // ---- weight prep (level-1 FFMA layers) ----
    WPrepAll P;
    P.w1[0] = g1W1_0; P.w2[0] = g1W2_0; P.K[0] = 32; P.off[0] = 0;
    P.w1[1] = g1W1_1; P.w2[1] = g1W2_1; P.K[1] = 64; P.off[1] = 32;
    P.w1[2] = g1W1_2; P.w2[2] = g1W2_2; P.K[2] = 64; P.off[2] = 96;
    prep_weights<<<3, 256>>>(P, Wt);

    const int* e1s = edge_index;  const int* e1d = edge_index + E1;
    const int* e2s = two_edges;   const int* e2d = two_edges + E2;
    const int* e3s = three_edges; const int* e3d = three_edges + E3;

    auto sc_grid = [](int E) { return (int)(((long long)E * 16 + 255) / 256); };

    const size_t sm32 = (64 * 32 + 32 * 128) * 4;
    const size_t sm64 = (64 * 64 + 32 * 128) * 4;

    // ---- level 1 (3 layers, exact FFMA); h holds PRE-activation ----
    gemm_dual<32><<<NNODES / 64, 256, sm32>>>(x, Wt + 0 * 128, hA, msg1, 0);
    scatter_add<<<sc_grid(E1), 256>>>((const float4*)msg1, e1s, e1d, E1, hA);

    gemm_dual<64><<<NNODES / 64, 256, sm64>>>(hA, Wt + 32 * 128, hB, msg1, 1);
    scatter_add<<<sc_grid(E1), 256>>>((const float4*)msg1, e1s, e1d, E1, hB);

    gemm_dual<64><<<NNODES / 64, 256, sm64>>>(hB, Wt + 96 * 128, hA, msg1, 1);
    scatter_add<<<sc_grid(E1), 256>>>((const float4*)msg1, e1s, e1d, E1, hA);

    seg_reduce<<<GG, 256>>>(hA, NPER, emb, 0);

    // ---- level 2 (2 layers, tf32 mma) ----
    gemm_mma<128, 2><<<N2 / 128, 256, SM_K128>>>(hA, gu2, gv2, nullptr, iso2,
                                                 g2W1_0, g2W2_0, 129,
                                                 h2A, msg2, 1);
    scatter_add<<<sc_grid(E2), 256>>>((const float4*)msg2, e2s, e2d, E2, h2A);

    gemm_mma<64, 0><<<N2 / 128, 256, SM_K64>>>(h2A, nullptr, nullptr, nullptr, nullptr,
                                               g2W1_1, g2W2_1, 64,
                                               h2B, msg2, 1);
    scatter_add<<<sc_grid(E2), 256>>>((const float4*)msg2, e2s, e2d, E2, h2B);

    seg_reduce<<<GG, 256>>>(h2B, P2, emb, H);

    // ---- level 3 (2 layers, tf32 mma) ----
    gemm_mma<192, 3><<<N3 / 128, 256, SM_K192>>>(hA, ga3, gb3, gc3, iso3,
                                                 g3W1_0, g3W2_0, 196,
                                                 h3A, msg3, 1);
    scatter_add<<<sc_grid(E3), 256>>>((const float4*)msg3, e3s, e3d, E3, h3A);

    gemm_mma<64, 0><<<N3 / 128, 256, SM_K64>>>(h3A, nullptr, nullptr, nullptr, nullptr,
                                               g3W1_1, g3W2_1, 64,
                                               h3B, msg3, 1);
    scatter_add<<<sc_grid(E3), 256>>>((const float4*)msg3, e3s, e3d, E3, h3B);

    seg_reduce<<<GG, 256>>>(h3B, P3, emb, 2 * H);

    // ---- head ----
    head<<<GG, H>>>(emb, cW1, cb1, cW2, cb2, out);
}